// round 15
// baseline (speedup 1.0000x reference)
#include <cuda_runtime.h>
#include <cuda_bf16.h>
#include <cuda_fp16.h>
#include <cstdint>

// ---------------------------------------------------------------------------
// Problem constants
// ---------------------------------------------------------------------------
#define BB 2
#define SS 2048
#define DD 1024
#define HH 16
#define RR 64
#define BH (BB * HH)   // 32
#define NEL (BB * SS * DD)

// ---------------------------------------------------------------------------
// mma.sync helpers (baseline PTX, plain sm_100 target)
// ---------------------------------------------------------------------------
__device__ __forceinline__ uint32_t smem_u32(const void* p) {
    uint32_t a;
    asm("{ .reg .u64 t; cvta.to.shared.u64 t, %1; cvt.u32.u64 %0, t; }"
        : "=r"(a) : "l"(p));
    return a;
}
__device__ __forceinline__ void ldm_x4(uint32_t* r, uint32_t addr) {
    asm volatile("ldmatrix.sync.aligned.m8n8.x4.shared.b16 {%0,%1,%2,%3}, [%4];"
                 : "=r"(r[0]), "=r"(r[1]), "=r"(r[2]), "=r"(r[3]) : "r"(addr));
}
__device__ __forceinline__ void ldm_x4_t(uint32_t* r, uint32_t addr) {
    asm volatile("ldmatrix.sync.aligned.m8n8.x4.trans.shared.b16 {%0,%1,%2,%3}, [%4];"
                 : "=r"(r[0]), "=r"(r[1]), "=r"(r[2]), "=r"(r[3]) : "r"(addr));
}
__device__ __forceinline__ void mma_bf16(float* c, const uint32_t* a,
                                         const uint32_t* b) {
    asm volatile(
        "mma.sync.aligned.m16n8k16.row.col.f32.bf16.bf16.f32 "
        "{%0,%1,%2,%3}, {%4,%5,%6,%7}, {%8,%9}, {%0,%1,%2,%3};"
        : "+f"(c[0]), "+f"(c[1]), "+f"(c[2]), "+f"(c[3])
        : "r"(a[0]), "r"(a[1]), "r"(a[2]), "r"(a[3]), "r"(b[0]), "r"(b[1]));
}
__device__ __forceinline__ void mma_f16(float* c, const uint32_t* a,
                                        const uint32_t* b) {
    asm volatile(
        "mma.sync.aligned.m16n8k16.row.col.f32.f16.f16.f32 "
        "{%0,%1,%2,%3}, {%4,%5,%6,%7}, {%8,%9}, {%0,%1,%2,%3};"
        : "+f"(c[0]), "+f"(c[1]), "+f"(c[2]), "+f"(c[3])
        : "r"(a[0]), "r"(a[1]), "r"(a[2]), "r"(a[3]), "r"(b[0]), "r"(b[1]));
}
__device__ __forceinline__ void cp16(uint32_t dst, const void* src) {
    asm volatile("cp.async.cg.shared.global [%0], [%1], 16;"
                 :: "r"(dst), "l"(__cvta_generic_to_global(src)));
}
#define CP_COMMIT() asm volatile("cp.async.commit_group;" ::: "memory")
#define CP_WAIT0()  asm volatile("cp.async.wait_group 0;" ::: "memory")
#define CP_WAIT1()  asm volatile("cp.async.wait_group 1;" ::: "memory")

__device__ __forceinline__ uint32_t swz(uint32_t o) { return o ^ ((o >> 3) & 0x70); }

__device__ __forceinline__ float ex2f(float x) {
    float y;
    asm("ex2.approx.ftz.f32 %0, %1;" : "=f"(y) : "f"(x));
    return y;
}
__device__ __forceinline__ float rcpf(float x) {
    float y;
    asm("rcp.approx.ftz.f32 %0, %1;" : "=f"(y) : "f"(x));
    return y;
}

// Split a float pair into bf16 hi/lo packed u32s (rn rounding).
__device__ __forceinline__ void splitpair(float x, float y,
                                          uint32_t& h, uint32_t& l) {
    asm("cvt.rn.bf16x2.f32 %0, %1, %2;" : "=r"(h) : "f"(y), "f"(x));
    float hx = __uint_as_float(h << 16);
    float hy = __uint_as_float(h & 0xFFFF0000u);
    asm("cvt.rn.bf16x2.f32 %0, %1, %2;" : "=r"(l) : "f"(y - hy), "f"(x - hx));
}
__device__ __forceinline__ uint32_t packh2(float x, float y) {
    __half2 H = __floats2half2_rn(x, y);
    return *reinterpret_cast<uint32_t*>(&H);
}

// ---------------------------------------------------------------------------
// Scratch
// ---------------------------------------------------------------------------
__device__ __nv_bfloat16 g_qs[2][NEL];
__device__ __nv_bfloat16 g_ks[2][NEL];
__device__ __half        g_vh16[NEL];           // v input, single fp16 plane
__device__ __nv_bfloat16 g_wqT[2][DD * DD];
__device__ __nv_bfloat16 g_wkT[2][DD * DD];
__device__ __half        g_wvH[2][DD * DD];     // wv fp16 hi/lo, transposed
__device__ __half        g_woH[2][DD * DD];     // wo fp16 hi/lo, transposed
// projection outputs, [b,h,s,r] layout:
//   Q/K bf16 hi/lo planes (Q pre-scaled by 0.125*log2e, exp2 domain)
//   V  single fp16 plane
__device__ __nv_bfloat16 g_Qb[2][BH * SS * RR];
__device__ __nv_bfloat16 g_Kb[2][BH * SS * RR];
__device__ __half        g_Vh[BH * SS * RR];
// attention output, single fp16 plane, [z][s][r] == flat [4096][1024]
__device__ __half        g_oh[NEL];

// ---------------------------------------------------------------------------
// fp32 -> split converters. sel 0/1 (q,k): bf16 hi/lo. sel 2 (v): fp16 single.
// ---------------------------------------------------------------------------
__global__ void __launch_bounds__(256) conv_rows_kernel(
    const float* __restrict__ q, const float* __restrict__ k,
    const float* __restrict__ v)
{
    const int sel = blockIdx.y;
    const float* src = (sel == 0) ? q : (sel == 1) ? k : v;

    if (sel < 2) {
        __nv_bfloat16* d0 = (sel == 0) ? g_qs[0] : g_ks[0];
        __nv_bfloat16* d1 = (sel == 0) ? g_qs[1] : g_ks[1];
        for (int i = (blockIdx.x * blockDim.x + threadIdx.x) * 4; i < NEL;
             i += gridDim.x * blockDim.x * 4) {
            float4 x = *reinterpret_cast<const float4*>(src + i);
            uint32_t h0, l0, h1, l1;
            splitpair(x.x, x.y, h0, l0);
            splitpair(x.z, x.w, h1, l1);
            *reinterpret_cast<uint2*>(d0 + i) = make_uint2(h0, h1);
            *reinterpret_cast<uint2*>(d1 + i) = make_uint2(l0, l1);
        }
    } else {
        for (int i = (blockIdx.x * blockDim.x + threadIdx.x) * 4; i < NEL;
             i += gridDim.x * blockDim.x * 4) {
            float4 x = *reinterpret_cast<const float4*>(src + i);
            *reinterpret_cast<uint2*>(g_vh16 + i) =
                make_uint2(packh2(x.x, x.y), packh2(x.z, x.w));
        }
    }
}

// Weight transpose + split. sel 0/1: bf16 planes; sel 2 (wv) / 3 (wo): fp16.
__global__ void __launch_bounds__(256) conv_w_kernel(
    const float* __restrict__ wq, const float* __restrict__ wk,
    const float* __restrict__ wv, const float* __restrict__ wo)
{
    const int sel = blockIdx.z;
    const float* W = (sel == 0) ? wq : (sel == 1) ? wk : (sel == 2) ? wv : wo;

    __shared__ float tile[32][33];
    const int tx = threadIdx.x & 31;
    const int ty = threadIdx.x >> 5;
    const int ct = blockIdx.x;
    const int rt = blockIdx.y;

    #pragma unroll
    for (int i = 0; i < 4; i++) {
        const int d = rt * 32 + ty + i * 8;
        const int n = ct * 32 + tx;
        size_t idx;
        if (sel < 3) idx = ((size_t)(n >> 6) * DD + d) * RR + (n & 63);
        else         idx = (size_t)d * DD + n;
        tile[ty + i * 8][tx] = W[idx];
    }
    __syncthreads();
    #pragma unroll
    for (int i = 0; i < 4; i++) {
        const int nl = ty + i * 8;
        const int n  = ct * 32 + nl;
        const int d  = rt * 32 + tx;
        float x = tile[tx][nl];
        size_t o = (size_t)n * DD + d;
        if (sel < 2) {
            __nv_bfloat16* d0 = (sel == 0) ? g_wqT[0] : g_wkT[0];
            __nv_bfloat16* d1 = (sel == 0) ? g_wqT[1] : g_wkT[1];
            __nv_bfloat16 b0 = __float2bfloat16(x);
            d0[o] = b0;
            d1[o] = __float2bfloat16(x - __bfloat162float(b0));
        } else {
            __half* d0 = (sel == 2) ? g_wvH[0] : g_woH[0];
            __half* d1 = (sel == 2) ? g_wvH[1] : g_woH[1];
            __half h0 = __float2half_rn(x);
            d0[o] = h0;
            d1[o] = __float2half_rn(x - __half2float(h0));
        }
    }
}

// ---------------------------------------------------------------------------
// mma.sync split-bf16 GEMM for Q/K projections (48-stage, 3 terms).
// ---------------------------------------------------------------------------
#define GEMM_SMEM 65536

__global__ void __launch_bounds__(256) gemm_kernel()
{
    const int kind = blockIdx.z;           // 0 = Q, 1 = K
    const __nv_bfloat16 *Ax[2], *Bx[2];
    __nv_bfloat16 *P0, *P1;
    float scale = 1.0f;
    if (kind == 0) { Ax[0] = g_qs[0]; Ax[1] = g_qs[1];
                     Bx[0] = g_wqT[0]; Bx[1] = g_wqT[1];
                     P0 = g_Qb[0]; P1 = g_Qb[1];
                     scale = 0.125f * 1.4426950408889634f; }
    else           { Ax[0] = g_ks[0]; Ax[1] = g_ks[1];
                     Bx[0] = g_wkT[0]; Bx[1] = g_wkT[1];
                     P0 = g_Kb[0]; P1 = g_Kb[1]; }
    const int ti[3] = {0, 0, 1};
    const int tj[3] = {0, 1, 0};
    const int NST = 48;

    extern __shared__ char smem[];
    const uint32_t sb = smem_u32(smem);
    const int t      = threadIdx.x;
    const int lane   = t & 31;
    const int wid    = t >> 5;
    const int warp_m = wid >> 2;
    const int warp_n = wid & 3;
    const int m0 = blockIdx.y * 128;
    const int n0 = blockIdx.x * 128;

    float acc[4][4][4];
    #pragma unroll
    for (int a = 0; a < 4; a++)
        #pragma unroll
        for (int b = 0; b < 4; b++)
            #pragma unroll
            for (int c = 0; c < 4; c++) acc[a][b][c] = 0.f;

    const int a_row  = warp_m * 64 + (lane & 15);
    const int a_koff = (lane >> 4) * 16;
    const int b_row  = warp_n * 32 + (lane & 7) + ((lane >> 4) & 1) * 8;
    const int b_koff = ((lane >> 3) & 1) * 16;

    {
        const uint32_t abase = sb, bbase = sb + 16384;
        #pragma unroll
        for (int it = 0; it < 4; it++) {
            const int cid = it * 256 + t;
            const int row = cid >> 3, c16 = cid & 7;
            cp16(abase + swz(row * 128 + c16 * 16),
                 Ax[0] + (size_t)(m0 + row) * DD + c16 * 8);
            cp16(bbase + swz(row * 128 + c16 * 16),
                 Bx[0] + (size_t)(n0 + row) * DD + c16 * 8);
        }
        CP_COMMIT();
    }

    for (int s = 0; s < NST; s++) {
        CP_WAIT0();
        __syncthreads();
        if (s + 1 < NST) {
            const int sn = s + 1;
            const int tt = sn >> 4;
            const int k0 = (sn & 15) * 64;
            const __nv_bfloat16* Ag = Ax[ti[tt]];
            const __nv_bfloat16* Bg = Bx[tj[tt]];
            const uint32_t abase = sb + (sn & 1) * 32768;
            const uint32_t bbase = abase + 16384;
            #pragma unroll
            for (int it = 0; it < 4; it++) {
                const int cid = it * 256 + t;
                const int row = cid >> 3, c16 = cid & 7;
                cp16(abase + swz(row * 128 + c16 * 16),
                     Ag + (size_t)(m0 + row) * DD + k0 + c16 * 8);
                cp16(bbase + swz(row * 128 + c16 * 16),
                     Bg + (size_t)(n0 + row) * DD + k0 + c16 * 8);
            }
            CP_COMMIT();
        }
        const uint32_t abase = sb + (s & 1) * 32768;
        const uint32_t bbase = abase + 16384;
        #pragma unroll
        for (int k16 = 0; k16 < 64; k16 += 16) {
            uint32_t ar[4][4], br[4][2];
            #pragma unroll
            for (int mi = 0; mi < 4; mi++) {
                const int row = a_row + mi * 16;
                ldm_x4(ar[mi], abase + swz(row * 128 + k16 * 2 + a_koff));
            }
            #pragma unroll
            for (int nb = 0; nb < 2; nb++) {
                const int n = b_row + nb * 16;
                uint32_t r[4];
                ldm_x4(r, bbase + swz(n * 128 + k16 * 2 + b_koff));
                br[nb * 2][0] = r[0]; br[nb * 2][1] = r[1];
                br[nb * 2 + 1][0] = r[2]; br[nb * 2 + 1][1] = r[3];
            }
            #pragma unroll
            for (int mi = 0; mi < 4; mi++)
                #pragma unroll
                for (int ni = 0; ni < 4; ni++)
                    mma_bf16(acc[mi][ni], ar[mi], br[ni]);
        }
    }

    // epilogue -> bf16 hi/lo planes in [b,h,s,r]
    #pragma unroll
    for (int mi = 0; mi < 4; mi++) {
        #pragma unroll
        for (int ni = 0; ni < 4; ni++) {
            const int r0 = m0 + warp_m * 64 + mi * 16 + (lane >> 2);
            const int c  = n0 + warp_n * 32 + ni * 8 + (lane & 3) * 2;
            #pragma unroll
            for (int half = 0; half < 2; half++) {
                const int m = r0 + half * 8;
                float v0 = acc[mi][ni][half * 2] * scale;
                float v1 = acc[mi][ni][half * 2 + 1] * scale;
                const int h = c >> 6, r = c & 63;
                const int b = m >> 11, sl = m & 2047;
                size_t idx = (((size_t)b * HH + h) * SS + sl) * RR + r;
                uint32_t hh, ll;
                splitpair(v0, v1, hh, ll);
                *reinterpret_cast<uint32_t*>(&P0[idx]) = hh;
                *reinterpret_cast<uint32_t*>(&P1[idx]) = ll;
            }
        }
    }
}

// ---------------------------------------------------------------------------
// fp16 2-term GEMM: tile 128x64, grid (16,32) = 512 CTAs, 3-stage cp.async.
//   kind 0: V projection  (A=g_vh16, B=g_wvH) -> g_Vh packed [b,h,s,r]
//   kind 1: out projection (A=g_oh,  B=g_woH) -> fp32 outC
//   Warp layout 4x2 (warp tile 32x32). Stage = A 16KB + B 8KB = 24KB.
// ---------------------------------------------------------------------------
#define F16_SMEM (3 * 24576)   // 73728

__global__ void __launch_bounds__(256) f16gemm_kernel(float* __restrict__ outC,
                                                      int kind)
{
    const __half* Ag = (kind == 0) ? g_vh16 : g_oh;
    const __half* Bp[2] = {(kind == 0) ? g_wvH[0] : g_woH[0],
                           (kind == 0) ? g_wvH[1] : g_woH[1]};
    const int NST = 32;
    extern __shared__ char smem[];
    const uint32_t sb = smem_u32(smem);
    const int t      = threadIdx.x;
    const int lane   = t & 31;
    const int wid    = t >> 5;
    const int warp_m = wid >> 1;          // 0..3 (32 rows each)
    const int warp_n = wid & 1;           // 0..1 (32 cols each)
    const int m0 = blockIdx.y * 128;
    const int n0 = blockIdx.x * 64;

    float acc[2][4][4];
    #pragma unroll
    for (int a = 0; a < 2; a++)
        #pragma unroll
        for (int b = 0; b < 4; b++)
            #pragma unroll
            for (int c = 0; c < 4; c++) acc[a][b][c] = 0.f;

    const int a_row  = warp_m * 32 + (lane & 15);
    const int a_koff = (lane >> 4) * 16;
    const int b_row  = warp_n * 32 + (lane & 7) + ((lane >> 4) & 1) * 8;
    const int b_koff = ((lane >> 3) & 1) * 16;

    // stage loader: buf = sn % 3, A at buf*24576, B at +16384
    #define F16_LOAD(sn)                                                      \
    do {                                                                      \
        const int _tt = (sn) >> 4;                                            \
        const int _k0 = ((sn) & 15) * 64;                                     \
        const uint32_t _ab = sb + ((sn) % 3) * 24576u;                        \
        const uint32_t _bb = _ab + 16384u;                                    \
        _Pragma("unroll")                                                     \
        for (int it = 0; it < 4; it++) {                                      \
            const int cid = it * 256 + t;                                     \
            const int row = cid >> 3, c16 = cid & 7;                          \
            cp16(_ab + swz(row * 128 + c16 * 16),                             \
                 Ag + (size_t)(m0 + row) * DD + _k0 + c16 * 8);               \
        }                                                                     \
        _Pragma("unroll")                                                     \
        for (int it = 0; it < 2; it++) {                                      \
            const int cid = it * 256 + t;                                     \
            const int row = cid >> 3, c16 = cid & 7;                          \
            cp16(_bb + swz(row * 128 + c16 * 16),                             \
                 Bp[_tt] + (size_t)(n0 + row) * DD + _k0 + c16 * 8);          \
        }                                                                     \
        CP_COMMIT();                                                          \
    } while (0)

    F16_LOAD(0);
    F16_LOAD(1);

    for (int s = 0; s < NST; s++) {
        if (s == NST - 1) CP_WAIT0(); else CP_WAIT1();
        __syncthreads();
        if (s + 2 < NST) F16_LOAD(s + 2);

        const uint32_t abase = sb + (s % 3) * 24576u;
        const uint32_t bbase = abase + 16384u;
        #pragma unroll
        for (int k16 = 0; k16 < 64; k16 += 16) {
            uint32_t ar[2][4], br[4][2];
            #pragma unroll
            for (int mi = 0; mi < 2; mi++) {
                const int row = a_row + mi * 16;
                ldm_x4(ar[mi], abase + swz(row * 128 + k16 * 2 + a_koff));
            }
            #pragma unroll
            for (int nb = 0; nb < 2; nb++) {
                const int n = b_row + nb * 16;
                uint32_t r[4];
                ldm_x4(r, bbase + swz(n * 128 + k16 * 2 + b_koff));
                br[nb * 2][0] = r[0]; br[nb * 2][1] = r[1];
                br[nb * 2 + 1][0] = r[2]; br[nb * 2 + 1][1] = r[3];
            }
            #pragma unroll
            for (int mi = 0; mi < 2; mi++)
                #pragma unroll
                for (int ni = 0; ni < 4; ni++)
                    mma_f16(acc[mi][ni], ar[mi], br[ni]);
        }
    }
    #undef F16_LOAD

    #pragma unroll
    for (int mi = 0; mi < 2; mi++) {
        #pragma unroll
        for (int ni = 0; ni < 4; ni++) {
            const int r0 = m0 + warp_m * 32 + mi * 16 + (lane >> 2);
            const int c  = n0 + warp_n * 32 + ni * 8 + (lane & 3) * 2;
            #pragma unroll
            for (int half = 0; half < 2; half++) {
                const int m = r0 + half * 8;
                float v0 = acc[mi][ni][half * 2];
                float v1 = acc[mi][ni][half * 2 + 1];
                if (kind == 0) {
                    const int h = c >> 6, r = c & 63;
                    const int b = m >> 11, sl = m & 2047;
                    size_t idx = (((size_t)b * HH + h) * SS + sl) * RR + r;
                    *reinterpret_cast<uint32_t*>(&g_Vh[idx]) = packh2(v0, v1);
                } else {
                    *reinterpret_cast<float2*>(&outC[(size_t)m * DD + c]) =
                        make_float2(v0, v1);
                }
            }
        }
    }
}

// ---------------------------------------------------------------------------
// Tensor-core flash attention (unchanged from the 483us version).
// ---------------------------------------------------------------------------
#define ATT_SMEM 81920

__global__ void __launch_bounds__(256, 2) attn_kernel()
{
    const int z  = blockIdx.y;
    const int s0 = blockIdx.x * 128;
    extern __shared__ char sm[];
    const uint32_t sb = smem_u32(sm);
    const int t = threadIdx.x, lane = t & 31, wid = t >> 5;
    const size_t zoff = (size_t)z * SS * RR;

    #define QOFF(p)      (sb + (p) * 16384u)
    #define KOFF(bf, p)  (sb + 32768u + (bf) * 24576u + (p) * 8192u)
    #define VOFF(bf)     (sb + 32768u + (bf) * 24576u + 16384u)

    #pragma unroll
    for (int p = 0; p < 2; p++) {
        const __nv_bfloat16* src = g_Qb[p] + zoff + (size_t)s0 * RR;
        #pragma unroll
        for (int it = 0; it < 4; it++) {
            const int cid = it * 256 + t;
            const int row = cid >> 3, c16 = cid & 7;
            cp16(QOFF(p) + swz(row * 128 + c16 * 16), src + row * 64 + c16 * 8);
        }
    }
    #pragma unroll
    for (int it = 0; it < 2; it++) {
        const int cid = it * 256 + t;
        const int row = cid >> 3, c16 = cid & 7;
        cp16(KOFF(0, 0) + swz(row * 128 + c16 * 16),
             g_Kb[0] + zoff + (size_t)row * RR + c16 * 8);
        cp16(KOFF(0, 1) + swz(row * 128 + c16 * 16),
             g_Kb[1] + zoff + (size_t)row * RR + c16 * 8);
        cp16(VOFF(0) + swz(row * 128 + c16 * 16),
             g_Vh + zoff + (size_t)row * RR + c16 * 8);
    }
    CP_COMMIT();

    float m0r = -3.0e38f, m1r = -3.0e38f, l0r = 0.f, l1r = 0.f;
    float oa[8][4];
    #pragma unroll
    for (int b = 0; b < 8; b++)
        #pragma unroll
        for (int c = 0; c < 4; c++) oa[b][c] = 0.f;

    for (int s = 0; s < 32; s++) {
        const int buf = s & 1;
        CP_WAIT0();
        __syncthreads();
        if (s + 1 < 32) {
            const int nb = (s + 1) & 1;
            const int kv = (s + 1) * 64;
            #pragma unroll
            for (int it = 0; it < 2; it++) {
                const int cid = it * 256 + t;
                const int row = cid >> 3, c16 = cid & 7;
                cp16(KOFF(nb, 0) + swz(row * 128 + c16 * 16),
                     g_Kb[0] + zoff + (size_t)(kv + row) * RR + c16 * 8);
                cp16(KOFF(nb, 1) + swz(row * 128 + c16 * 16),
                     g_Kb[1] + zoff + (size_t)(kv + row) * RR + c16 * 8);
                cp16(VOFF(nb) + swz(row * 128 + c16 * 16),
                     g_Vh + zoff + (size_t)(kv + row) * RR + c16 * 8);
            }
            CP_COMMIT();
        }

        // ---- GEMM1: S = Q K^T (bf16, 3 split terms) ----
        float sa[8][4];
        #pragma unroll
        for (int b = 0; b < 8; b++)
            #pragma unroll
            for (int c = 0; c < 4; c++) sa[b][c] = 0.f;

        #pragma unroll
        for (int kb = 0; kb < 4; kb++) {
            uint32_t aq[2][4];
            const int arow = wid * 16 + (lane & 15);
            const int akoff = kb * 32 + (lane >> 4) * 16;
            #pragma unroll
            for (int p = 0; p < 2; p++)
                ldm_x4(aq[p], QOFF(p) + swz(arow * 128 + akoff));
            #pragma unroll
            for (int g = 0; g < 4; g++) {
                uint32_t bk[2][4];
                const int brow = g * 16 + (lane & 7) + ((lane >> 4) & 1) * 8;
                const int bkoff = kb * 32 + ((lane >> 3) & 1) * 16;
                #pragma unroll
                for (int p = 0; p < 2; p++)
                    ldm_x4(bk[p], KOFF(buf, p) + swz(brow * 128 + bkoff));
                mma_bf16(sa[2 * g],     aq[0], &bk[0][0]);   // hi*hi
                mma_bf16(sa[2 * g + 1], aq[0], &bk[0][2]);
                mma_bf16(sa[2 * g],     aq[0], &bk[1][0]);   // hi*lo
                mma_bf16(sa[2 * g + 1], aq[0], &bk[1][2]);
                mma_bf16(sa[2 * g],     aq[1], &bk[0][0]);   // lo*hi
                mma_bf16(sa[2 * g + 1], aq[1], &bk[0][2]);
            }
        }

        // ---- online softmax (exp2 domain, MUFU ex2) ----
        float mt0 = -3.0e38f, mt1 = -3.0e38f;
        #pragma unroll
        for (int b = 0; b < 8; b++) {
            mt0 = fmaxf(mt0, fmaxf(sa[b][0], sa[b][1]));
            mt1 = fmaxf(mt1, fmaxf(sa[b][2], sa[b][3]));
        }
        mt0 = fmaxf(mt0, __shfl_xor_sync(0xffffffffu, mt0, 1));
        mt0 = fmaxf(mt0, __shfl_xor_sync(0xffffffffu, mt0, 2));
        mt1 = fmaxf(mt1, __shfl_xor_sync(0xffffffffu, mt1, 1));
        mt1 = fmaxf(mt1, __shfl_xor_sync(0xffffffffu, mt1, 2));
        const float mn0 = fmaxf(m0r, mt0), mn1 = fmaxf(m1r, mt1);
        const float al0 = ex2f(m0r - mn0), al1 = ex2f(m1r - mn1);
        m0r = mn0; m1r = mn1;
        float rs0 = 0.f, rs1 = 0.f;
        #pragma unroll
        for (int b = 0; b < 8; b++) {
            sa[b][0] = ex2f(sa[b][0] - mn0);
            sa[b][1] = ex2f(sa[b][1] - mn0);
            sa[b][2] = ex2f(sa[b][2] - mn1);
            sa[b][3] = ex2f(sa[b][3] - mn1);
            rs0 += sa[b][0] + sa[b][1];
            rs1 += sa[b][2] + sa[b][3];
        }
        rs0 += __shfl_xor_sync(0xffffffffu, rs0, 1);
        rs0 += __shfl_xor_sync(0xffffffffu, rs0, 2);
        rs1 += __shfl_xor_sync(0xffffffffu, rs1, 1);
        rs1 += __shfl_xor_sync(0xffffffffu, rs1, 2);
        l0r = l0r * al0 + rs0;
        l1r = l1r * al1 + rs1;
        #pragma unroll
        for (int b = 0; b < 8; b++) {
            oa[b][0] *= al0; oa[b][1] *= al0;
            oa[b][2] *= al1; oa[b][3] *= al1;
        }

        // ---- GEMM2: O += P V (fp16 P, single fp16 V) ----
        #pragma unroll
        for (int kb = 0; kb < 4; kb++) {
            uint32_t pp[4];
            pp[0] = packh2(sa[2 * kb][0],     sa[2 * kb][1]);
            pp[1] = packh2(sa[2 * kb][2],     sa[2 * kb][3]);
            pp[2] = packh2(sa[2 * kb + 1][0], sa[2 * kb + 1][1]);
            pp[3] = packh2(sa[2 * kb + 1][2], sa[2 * kb + 1][3]);
            #pragma unroll
            for (int g = 0; g < 4; g++) {
                uint32_t bv[4];
                const int trow = kb * 16 + (lane & 7) + ((lane >> 3) & 1) * 8;
                const int rbyte = g * 32 + ((lane >> 4) & 1) * 16;
                ldm_x4_t(bv, VOFF(buf) + swz(trow * 128 + rbyte));
                mma_f16(oa[2 * g],     pp, &bv[0]);
                mma_f16(oa[2 * g + 1], pp, &bv[2]);
            }
        }
    }

    // ---- epilogue: O/l -> g_oh single fp16 plane ----
    const float i0 = rcpf(l0r), i1 = rcpf(l1r);
    #pragma unroll
    for (int b = 0; b < 8; b++) {
        const int r   = b * 8 + (lane & 3) * 2;
        const int r0w = s0 + wid * 16 + (lane >> 2);
        size_t idx = zoff + (size_t)r0w * RR + r;
        *reinterpret_cast<uint32_t*>(&g_oh[idx]) =
            packh2(oa[b][0] * i0, oa[b][1] * i0);
        idx = zoff + (size_t)(r0w + 8) * RR + r;
        *reinterpret_cast<uint32_t*>(&g_oh[idx]) =
            packh2(oa[b][2] * i1, oa[b][3] * i1);
    }
    #undef QOFF
    #undef KOFF
    #undef VOFF
}

// ---------------------------------------------------------------------------
// Launch
// ---------------------------------------------------------------------------
extern "C" void kernel_launch(void* const* d_in, const int* in_sizes, int n_in,
                              void* d_out, int out_size)
{
    const float* q  = (const float*)d_in[0];
    const float* k  = (const float*)d_in[1];
    const float* v  = (const float*)d_in[2];
    const float* wq = (const float*)d_in[3];
    const float* wk = (const float*)d_in[4];
    const float* wv = (const float*)d_in[5];
    const float* wo = (const float*)d_in[6];
    float* out = (float*)d_out;

    (void)in_sizes; (void)n_in; (void)out_size;

    cudaFuncSetAttribute(gemm_kernel,
                         cudaFuncAttributeMaxDynamicSharedMemorySize, GEMM_SMEM);
    cudaFuncSetAttribute(f16gemm_kernel,
                         cudaFuncAttributeMaxDynamicSharedMemorySize, F16_SMEM);
    cudaFuncSetAttribute(attn_kernel,
                         cudaFuncAttributeMaxDynamicSharedMemorySize, ATT_SMEM);

    // 1) split inputs + weights
    conv_rows_kernel<<<dim3(1024, 3), 256>>>(q, k, v);
    conv_w_kernel<<<dim3(32, 32, 4), 256>>>(wq, wk, wv, wo);

    // 2) Q/K projections (bf16 3-term); V projection (fp16 2-term)
    gemm_kernel<<<dim3(8, 32, 2), 256, GEMM_SMEM>>>();
    f16gemm_kernel<<<dim3(16, 32), 256, F16_SMEM>>>(nullptr, 0);

    // 3) tensor-core flash attention -> g_oh
    attn_kernel<<<dim3(16, 32), 256, ATT_SMEM>>>();

    // 4) output projection (fp16 2-term) -> fp32 out
    f16gemm_kernel<<<dim3(16, 32), 256, F16_SMEM>>>(out, 1);
}

// round 16
// speedup vs baseline: 1.0260x; 1.0260x over previous
#include <cuda_runtime.h>
#include <cuda_bf16.h>
#include <cuda_fp16.h>
#include <cstdint>

// ---------------------------------------------------------------------------
// Problem constants
// ---------------------------------------------------------------------------
#define BB 2
#define SS 2048
#define DD 1024
#define HH 16
#define RR 64
#define BH (BB * HH)   // 32
#define NEL (BB * SS * DD)

// ---------------------------------------------------------------------------
// mma.sync helpers (baseline PTX, plain sm_100 target)
// ---------------------------------------------------------------------------
__device__ __forceinline__ uint32_t smem_u32(const void* p) {
    uint32_t a;
    asm("{ .reg .u64 t; cvta.to.shared.u64 t, %1; cvt.u32.u64 %0, t; }"
        : "=r"(a) : "l"(p));
    return a;
}
__device__ __forceinline__ void ldm_x4(uint32_t* r, uint32_t addr) {
    asm volatile("ldmatrix.sync.aligned.m8n8.x4.shared.b16 {%0,%1,%2,%3}, [%4];"
                 : "=r"(r[0]), "=r"(r[1]), "=r"(r[2]), "=r"(r[3]) : "r"(addr));
}
__device__ __forceinline__ void ldm_x4_t(uint32_t* r, uint32_t addr) {
    asm volatile("ldmatrix.sync.aligned.m8n8.x4.trans.shared.b16 {%0,%1,%2,%3}, [%4];"
                 : "=r"(r[0]), "=r"(r[1]), "=r"(r[2]), "=r"(r[3]) : "r"(addr));
}
__device__ __forceinline__ void mma_bf16(float* c, const uint32_t* a,
                                         const uint32_t* b) {
    asm volatile(
        "mma.sync.aligned.m16n8k16.row.col.f32.bf16.bf16.f32 "
        "{%0,%1,%2,%3}, {%4,%5,%6,%7}, {%8,%9}, {%0,%1,%2,%3};"
        : "+f"(c[0]), "+f"(c[1]), "+f"(c[2]), "+f"(c[3])
        : "r"(a[0]), "r"(a[1]), "r"(a[2]), "r"(a[3]), "r"(b[0]), "r"(b[1]));
}
__device__ __forceinline__ void mma_f16(float* c, const uint32_t* a,
                                        const uint32_t* b) {
    asm volatile(
        "mma.sync.aligned.m16n8k16.row.col.f32.f16.f16.f32 "
        "{%0,%1,%2,%3}, {%4,%5,%6,%7}, {%8,%9}, {%0,%1,%2,%3};"
        : "+f"(c[0]), "+f"(c[1]), "+f"(c[2]), "+f"(c[3])
        : "r"(a[0]), "r"(a[1]), "r"(a[2]), "r"(a[3]), "r"(b[0]), "r"(b[1]));
}
__device__ __forceinline__ void cp16(uint32_t dst, const void* src) {
    asm volatile("cp.async.cg.shared.global [%0], [%1], 16;"
                 :: "r"(dst), "l"(__cvta_generic_to_global(src)));
}
#define CP_COMMIT() asm volatile("cp.async.commit_group;" ::: "memory")
#define CP_WAIT0()  asm volatile("cp.async.wait_group 0;" ::: "memory")
#define CP_WAIT1()  asm volatile("cp.async.wait_group 1;" ::: "memory")

__device__ __forceinline__ uint32_t swz(uint32_t o) { return o ^ ((o >> 3) & 0x70); }

__device__ __forceinline__ float ex2f(float x) {
    float y;
    asm("ex2.approx.ftz.f32 %0, %1;" : "=f"(y) : "f"(x));
    return y;
}
__device__ __forceinline__ float rcpf(float x) {
    float y;
    asm("rcp.approx.ftz.f32 %0, %1;" : "=f"(y) : "f"(x));
    return y;
}

// Split a float pair into bf16 hi/lo packed u32s (rn rounding).
__device__ __forceinline__ void splitpair(float x, float y,
                                          uint32_t& h, uint32_t& l) {
    asm("cvt.rn.bf16x2.f32 %0, %1, %2;" : "=r"(h) : "f"(y), "f"(x));
    float hx = __uint_as_float(h << 16);
    float hy = __uint_as_float(h & 0xFFFF0000u);
    asm("cvt.rn.bf16x2.f32 %0, %1, %2;" : "=r"(l) : "f"(y - hy), "f"(x - hx));
}
__device__ __forceinline__ uint32_t packh2(float x, float y) {
    __half2 H = __floats2half2_rn(x, y);
    return *reinterpret_cast<uint32_t*>(&H);
}

// ---------------------------------------------------------------------------
// Scratch
// ---------------------------------------------------------------------------
__device__ __nv_bfloat16 g_qs[2][NEL];
__device__ __nv_bfloat16 g_ks[2][NEL];
__device__ __half        g_vh16[NEL];           // v input, single fp16 plane
__device__ __nv_bfloat16 g_wqT[2][DD * DD];
__device__ __nv_bfloat16 g_wkT[2][DD * DD];
__device__ __half        g_wvH[2][DD * DD];     // wv fp16 hi/lo, transposed
__device__ __half        g_woH[2][DD * DD];     // wo fp16 hi/lo, transposed
// projection outputs, [b,h,s,r] layout:
//   Q/K bf16 hi/lo planes (Q pre-scaled by 0.125*log2e, exp2 domain)
//   V  single fp16 plane
__device__ __nv_bfloat16 g_Qb[2][BH * SS * RR];
__device__ __nv_bfloat16 g_Kb[2][BH * SS * RR];
__device__ __half        g_Vh[BH * SS * RR];
// attention output, single fp16 plane, [z][s][r] == flat [4096][1024]
__device__ __half        g_oh[NEL];

// ---------------------------------------------------------------------------
// fp32 -> split converters. sel 0/1 (q,k): bf16 hi/lo. sel 2 (v): fp16 single.
// ---------------------------------------------------------------------------
__global__ void __launch_bounds__(256) conv_rows_kernel(
    const float* __restrict__ q, const float* __restrict__ k,
    const float* __restrict__ v)
{
    const int sel = blockIdx.y;
    const float* src = (sel == 0) ? q : (sel == 1) ? k : v;

    if (sel < 2) {
        __nv_bfloat16* d0 = (sel == 0) ? g_qs[0] : g_ks[0];
        __nv_bfloat16* d1 = (sel == 0) ? g_qs[1] : g_ks[1];
        for (int i = (blockIdx.x * blockDim.x + threadIdx.x) * 4; i < NEL;
             i += gridDim.x * blockDim.x * 4) {
            float4 x = *reinterpret_cast<const float4*>(src + i);
            uint32_t h0, l0, h1, l1;
            splitpair(x.x, x.y, h0, l0);
            splitpair(x.z, x.w, h1, l1);
            *reinterpret_cast<uint2*>(d0 + i) = make_uint2(h0, h1);
            *reinterpret_cast<uint2*>(d1 + i) = make_uint2(l0, l1);
        }
    } else {
        for (int i = (blockIdx.x * blockDim.x + threadIdx.x) * 4; i < NEL;
             i += gridDim.x * blockDim.x * 4) {
            float4 x = *reinterpret_cast<const float4*>(src + i);
            *reinterpret_cast<uint2*>(g_vh16 + i) =
                make_uint2(packh2(x.x, x.y), packh2(x.z, x.w));
        }
    }
}

// Weight transpose + split. sel 0/1: bf16 planes; sel 2 (wv) / 3 (wo): fp16.
__global__ void __launch_bounds__(256) conv_w_kernel(
    const float* __restrict__ wq, const float* __restrict__ wk,
    const float* __restrict__ wv, const float* __restrict__ wo)
{
    const int sel = blockIdx.z;
    const float* W = (sel == 0) ? wq : (sel == 1) ? wk : (sel == 2) ? wv : wo;

    __shared__ float tile[32][33];
    const int tx = threadIdx.x & 31;
    const int ty = threadIdx.x >> 5;
    const int ct = blockIdx.x;
    const int rt = blockIdx.y;

    #pragma unroll
    for (int i = 0; i < 4; i++) {
        const int d = rt * 32 + ty + i * 8;
        const int n = ct * 32 + tx;
        size_t idx;
        if (sel < 3) idx = ((size_t)(n >> 6) * DD + d) * RR + (n & 63);
        else         idx = (size_t)d * DD + n;
        tile[ty + i * 8][tx] = W[idx];
    }
    __syncthreads();
    #pragma unroll
    for (int i = 0; i < 4; i++) {
        const int nl = ty + i * 8;
        const int n  = ct * 32 + nl;
        const int d  = rt * 32 + tx;
        float x = tile[tx][nl];
        size_t o = (size_t)n * DD + d;
        if (sel < 2) {
            __nv_bfloat16* d0 = (sel == 0) ? g_wqT[0] : g_wkT[0];
            __nv_bfloat16* d1 = (sel == 0) ? g_wqT[1] : g_wkT[1];
            __nv_bfloat16 b0 = __float2bfloat16(x);
            d0[o] = b0;
            d1[o] = __float2bfloat16(x - __bfloat162float(b0));
        } else {
            __half* d0 = (sel == 2) ? g_wvH[0] : g_woH[0];
            __half* d1 = (sel == 2) ? g_wvH[1] : g_woH[1];
            __half h0 = __float2half_rn(x);
            d0[o] = h0;
            d1[o] = __float2half_rn(x - __half2float(h0));
        }
    }
}

// ---------------------------------------------------------------------------
// mma.sync split-bf16 GEMM for Q/K projections (48-stage, 3 terms).
// ---------------------------------------------------------------------------
#define GEMM_SMEM 65536

__global__ void __launch_bounds__(256) gemm_kernel()
{
    const int kind = blockIdx.z;           // 0 = Q, 1 = K
    const __nv_bfloat16 *Ax[2], *Bx[2];
    __nv_bfloat16 *P0, *P1;
    float scale = 1.0f;
    if (kind == 0) { Ax[0] = g_qs[0]; Ax[1] = g_qs[1];
                     Bx[0] = g_wqT[0]; Bx[1] = g_wqT[1];
                     P0 = g_Qb[0]; P1 = g_Qb[1];
                     scale = 0.125f * 1.4426950408889634f; }
    else           { Ax[0] = g_ks[0]; Ax[1] = g_ks[1];
                     Bx[0] = g_wkT[0]; Bx[1] = g_wkT[1];
                     P0 = g_Kb[0]; P1 = g_Kb[1]; }
    const int ti[3] = {0, 0, 1};
    const int tj[3] = {0, 1, 0};
    const int NST = 48;

    extern __shared__ char smem[];
    const uint32_t sb = smem_u32(smem);
    const int t      = threadIdx.x;
    const int lane   = t & 31;
    const int wid    = t >> 5;
    const int warp_m = wid >> 2;
    const int warp_n = wid & 3;
    const int m0 = blockIdx.y * 128;
    const int n0 = blockIdx.x * 128;

    float acc[4][4][4];
    #pragma unroll
    for (int a = 0; a < 4; a++)
        #pragma unroll
        for (int b = 0; b < 4; b++)
            #pragma unroll
            for (int c = 0; c < 4; c++) acc[a][b][c] = 0.f;

    const int a_row  = warp_m * 64 + (lane & 15);
    const int a_koff = (lane >> 4) * 16;
    const int b_row  = warp_n * 32 + (lane & 7) + ((lane >> 4) & 1) * 8;
    const int b_koff = ((lane >> 3) & 1) * 16;

    {
        const uint32_t abase = sb, bbase = sb + 16384;
        #pragma unroll
        for (int it = 0; it < 4; it++) {
            const int cid = it * 256 + t;
            const int row = cid >> 3, c16 = cid & 7;
            cp16(abase + swz(row * 128 + c16 * 16),
                 Ax[0] + (size_t)(m0 + row) * DD + c16 * 8);
            cp16(bbase + swz(row * 128 + c16 * 16),
                 Bx[0] + (size_t)(n0 + row) * DD + c16 * 8);
        }
        CP_COMMIT();
    }

    for (int s = 0; s < NST; s++) {
        CP_WAIT0();
        __syncthreads();
        if (s + 1 < NST) {
            const int sn = s + 1;
            const int tt = sn >> 4;
            const int k0 = (sn & 15) * 64;
            const __nv_bfloat16* Ag = Ax[ti[tt]];
            const __nv_bfloat16* Bg = Bx[tj[tt]];
            const uint32_t abase = sb + (sn & 1) * 32768;
            const uint32_t bbase = abase + 16384;
            #pragma unroll
            for (int it = 0; it < 4; it++) {
                const int cid = it * 256 + t;
                const int row = cid >> 3, c16 = cid & 7;
                cp16(abase + swz(row * 128 + c16 * 16),
                     Ag + (size_t)(m0 + row) * DD + k0 + c16 * 8);
                cp16(bbase + swz(row * 128 + c16 * 16),
                     Bg + (size_t)(n0 + row) * DD + k0 + c16 * 8);
            }
            CP_COMMIT();
        }
        const uint32_t abase = sb + (s & 1) * 32768;
        const uint32_t bbase = abase + 16384;
        #pragma unroll
        for (int k16 = 0; k16 < 64; k16 += 16) {
            uint32_t ar[4][4], br[4][2];
            #pragma unroll
            for (int mi = 0; mi < 4; mi++) {
                const int row = a_row + mi * 16;
                ldm_x4(ar[mi], abase + swz(row * 128 + k16 * 2 + a_koff));
            }
            #pragma unroll
            for (int nb = 0; nb < 2; nb++) {
                const int n = b_row + nb * 16;
                uint32_t r[4];
                ldm_x4(r, bbase + swz(n * 128 + k16 * 2 + b_koff));
                br[nb * 2][0] = r[0]; br[nb * 2][1] = r[1];
                br[nb * 2 + 1][0] = r[2]; br[nb * 2 + 1][1] = r[3];
            }
            #pragma unroll
            for (int mi = 0; mi < 4; mi++)
                #pragma unroll
                for (int ni = 0; ni < 4; ni++)
                    mma_bf16(acc[mi][ni], ar[mi], br[ni]);
        }
    }

    // epilogue -> bf16 hi/lo planes in [b,h,s,r]
    #pragma unroll
    for (int mi = 0; mi < 4; mi++) {
        #pragma unroll
        for (int ni = 0; ni < 4; ni++) {
            const int r0 = m0 + warp_m * 64 + mi * 16 + (lane >> 2);
            const int c  = n0 + warp_n * 32 + ni * 8 + (lane & 3) * 2;
            #pragma unroll
            for (int half = 0; half < 2; half++) {
                const int m = r0 + half * 8;
                float v0 = acc[mi][ni][half * 2] * scale;
                float v1 = acc[mi][ni][half * 2 + 1] * scale;
                const int h = c >> 6, r = c & 63;
                const int b = m >> 11, sl = m & 2047;
                size_t idx = (((size_t)b * HH + h) * SS + sl) * RR + r;
                uint32_t hh, ll;
                splitpair(v0, v1, hh, ll);
                *reinterpret_cast<uint32_t*>(&P0[idx]) = hh;
                *reinterpret_cast<uint32_t*>(&P1[idx]) = ll;
            }
        }
    }
}

// ---------------------------------------------------------------------------
// fp16 2-term GEMM: tile 128x128 (the proven R14 shape), 3-stage cp.async.
//   kind 0: V projection  (A=g_vh16, B=g_wvH) -> g_Vh packed [b,h,s,r]
//   kind 1: out projection (A=g_oh,  B=g_woH) -> fp32 outC
//   Stage = A 16KB + B 16KB = 32KB; 3 stages = 96KB; 2 CTAs/SM.
// ---------------------------------------------------------------------------
#define F16_SMEM (3 * 32768)   // 98304

__global__ void __launch_bounds__(256) f16gemm_kernel(float* __restrict__ outC,
                                                      int kind)
{
    const __half* Ag = (kind == 0) ? g_vh16 : g_oh;
    const __half* Bp[2] = {(kind == 0) ? g_wvH[0] : g_woH[0],
                           (kind == 0) ? g_wvH[1] : g_woH[1]};
    const int NST = 32;
    extern __shared__ char smem[];
    const uint32_t sb = smem_u32(smem);
    const int t      = threadIdx.x;
    const int lane   = t & 31;
    const int wid    = t >> 5;
    const int warp_m = wid >> 2;
    const int warp_n = wid & 3;
    const int m0 = blockIdx.y * 128;
    const int n0 = blockIdx.x * 128;

    float acc[4][4][4];
    #pragma unroll
    for (int a = 0; a < 4; a++)
        #pragma unroll
        for (int b = 0; b < 4; b++)
            #pragma unroll
            for (int c = 0; c < 4; c++) acc[a][b][c] = 0.f;

    const int a_row  = warp_m * 64 + (lane & 15);
    const int a_koff = (lane >> 4) * 16;
    const int b_row  = warp_n * 32 + (lane & 7) + ((lane >> 4) & 1) * 8;
    const int b_koff = ((lane >> 3) & 1) * 16;

    // stage loader: buf = sn % 3 at sb + buf*32768; A +0, B +16384
    #define F16_LOAD(sn)                                                      \
    do {                                                                      \
        const int _tt = (sn) >> 4;                                            \
        const int _k0 = ((sn) & 15) * 64;                                     \
        const uint32_t _ab = sb + ((sn) % 3) * 32768u;                        \
        const uint32_t _bb = _ab + 16384u;                                    \
        _Pragma("unroll")                                                     \
        for (int it = 0; it < 4; it++) {                                      \
            const int cid = it * 256 + t;                                     \
            const int row = cid >> 3, c16 = cid & 7;                          \
            cp16(_ab + swz(row * 128 + c16 * 16),                             \
                 Ag + (size_t)(m0 + row) * DD + _k0 + c16 * 8);               \
            cp16(_bb + swz(row * 128 + c16 * 16),                             \
                 Bp[_tt] + (size_t)(n0 + row) * DD + _k0 + c16 * 8);          \
        }                                                                     \
        CP_COMMIT();                                                          \
    } while (0)

    F16_LOAD(0);
    F16_LOAD(1);

    for (int s = 0; s < NST; s++) {
        if (s == NST - 1) CP_WAIT0(); else CP_WAIT1();
        __syncthreads();
        if (s + 2 < NST) F16_LOAD(s + 2);

        const uint32_t abase = sb + (s % 3) * 32768u;
        const uint32_t bbase = abase + 16384u;
        #pragma unroll
        for (int k16 = 0; k16 < 64; k16 += 16) {
            uint32_t ar[4][4], br[4][2];
            #pragma unroll
            for (int mi = 0; mi < 4; mi++) {
                const int row = a_row + mi * 16;
                ldm_x4(ar[mi], abase + swz(row * 128 + k16 * 2 + a_koff));
            }
            #pragma unroll
            for (int nb = 0; nb < 2; nb++) {
                const int n = b_row + nb * 16;
                uint32_t r[4];
                ldm_x4(r, bbase + swz(n * 128 + k16 * 2 + b_koff));
                br[nb * 2][0] = r[0]; br[nb * 2][1] = r[1];
                br[nb * 2 + 1][0] = r[2]; br[nb * 2 + 1][1] = r[3];
            }
            #pragma unroll
            for (int mi = 0; mi < 4; mi++)
                #pragma unroll
                for (int ni = 0; ni < 4; ni++)
                    mma_f16(acc[mi][ni], ar[mi], br[ni]);
        }
    }
    #undef F16_LOAD

    #pragma unroll
    for (int mi = 0; mi < 4; mi++) {
        #pragma unroll
        for (int ni = 0; ni < 4; ni++) {
            const int r0 = m0 + warp_m * 64 + mi * 16 + (lane >> 2);
            const int c  = n0 + warp_n * 32 + ni * 8 + (lane & 3) * 2;
            #pragma unroll
            for (int half = 0; half < 2; half++) {
                const int m = r0 + half * 8;
                float v0 = acc[mi][ni][half * 2];
                float v1 = acc[mi][ni][half * 2 + 1];
                if (kind == 0) {
                    const int h = c >> 6, r = c & 63;
                    const int b = m >> 11, sl = m & 2047;
                    size_t idx = (((size_t)b * HH + h) * SS + sl) * RR + r;
                    *reinterpret_cast<uint32_t*>(&g_Vh[idx]) = packh2(v0, v1);
                } else {
                    *reinterpret_cast<float2*>(&outC[(size_t)m * DD + c]) =
                        make_float2(v0, v1);
                }
            }
        }
    }
}

// ---------------------------------------------------------------------------
// Tensor-core flash attention (unchanged from the 483us version).
// ---------------------------------------------------------------------------
#define ATT_SMEM 81920

__global__ void __launch_bounds__(256, 2) attn_kernel()
{
    const int z  = blockIdx.y;
    const int s0 = blockIdx.x * 128;
    extern __shared__ char sm[];
    const uint32_t sb = smem_u32(sm);
    const int t = threadIdx.x, lane = t & 31, wid = t >> 5;
    const size_t zoff = (size_t)z * SS * RR;

    #define QOFF(p)      (sb + (p) * 16384u)
    #define KOFF(bf, p)  (sb + 32768u + (bf) * 24576u + (p) * 8192u)
    #define VOFF(bf)     (sb + 32768u + (bf) * 24576u + 16384u)

    #pragma unroll
    for (int p = 0; p < 2; p++) {
        const __nv_bfloat16* src = g_Qb[p] + zoff + (size_t)s0 * RR;
        #pragma unroll
        for (int it = 0; it < 4; it++) {
            const int cid = it * 256 + t;
            const int row = cid >> 3, c16 = cid & 7;
            cp16(QOFF(p) + swz(row * 128 + c16 * 16), src + row * 64 + c16 * 8);
        }
    }
    #pragma unroll
    for (int it = 0; it < 2; it++) {
        const int cid = it * 256 + t;
        const int row = cid >> 3, c16 = cid & 7;
        cp16(KOFF(0, 0) + swz(row * 128 + c16 * 16),
             g_Kb[0] + zoff + (size_t)row * RR + c16 * 8);
        cp16(KOFF(0, 1) + swz(row * 128 + c16 * 16),
             g_Kb[1] + zoff + (size_t)row * RR + c16 * 8);
        cp16(VOFF(0) + swz(row * 128 + c16 * 16),
             g_Vh + zoff + (size_t)row * RR + c16 * 8);
    }
    CP_COMMIT();

    float m0r = -3.0e38f, m1r = -3.0e38f, l0r = 0.f, l1r = 0.f;
    float oa[8][4];
    #pragma unroll
    for (int b = 0; b < 8; b++)
        #pragma unroll
        for (int c = 0; c < 4; c++) oa[b][c] = 0.f;

    for (int s = 0; s < 32; s++) {
        const int buf = s & 1;
        CP_WAIT0();
        __syncthreads();
        if (s + 1 < 32) {
            const int nb = (s + 1) & 1;
            const int kv = (s + 1) * 64;
            #pragma unroll
            for (int it = 0; it < 2; it++) {
                const int cid = it * 256 + t;
                const int row = cid >> 3, c16 = cid & 7;
                cp16(KOFF(nb, 0) + swz(row * 128 + c16 * 16),
                     g_Kb[0] + zoff + (size_t)(kv + row) * RR + c16 * 8);
                cp16(KOFF(nb, 1) + swz(row * 128 + c16 * 16),
                     g_Kb[1] + zoff + (size_t)(kv + row) * RR + c16 * 8);
                cp16(VOFF(nb) + swz(row * 128 + c16 * 16),
                     g_Vh + zoff + (size_t)(kv + row) * RR + c16 * 8);
            }
            CP_COMMIT();
        }

        // ---- GEMM1: S = Q K^T (bf16, 3 split terms) ----
        float sa[8][4];
        #pragma unroll
        for (int b = 0; b < 8; b++)
            #pragma unroll
            for (int c = 0; c < 4; c++) sa[b][c] = 0.f;

        #pragma unroll
        for (int kb = 0; kb < 4; kb++) {
            uint32_t aq[2][4];
            const int arow = wid * 16 + (lane & 15);
            const int akoff = kb * 32 + (lane >> 4) * 16;
            #pragma unroll
            for (int p = 0; p < 2; p++)
                ldm_x4(aq[p], QOFF(p) + swz(arow * 128 + akoff));
            #pragma unroll
            for (int g = 0; g < 4; g++) {
                uint32_t bk[2][4];
                const int brow = g * 16 + (lane & 7) + ((lane >> 4) & 1) * 8;
                const int bkoff = kb * 32 + ((lane >> 3) & 1) * 16;
                #pragma unroll
                for (int p = 0; p < 2; p++)
                    ldm_x4(bk[p], KOFF(buf, p) + swz(brow * 128 + bkoff));
                mma_bf16(sa[2 * g],     aq[0], &bk[0][0]);   // hi*hi
                mma_bf16(sa[2 * g + 1], aq[0], &bk[0][2]);
                mma_bf16(sa[2 * g],     aq[0], &bk[1][0]);   // hi*lo
                mma_bf16(sa[2 * g + 1], aq[0], &bk[1][2]);
                mma_bf16(sa[2 * g],     aq[1], &bk[0][0]);   // lo*hi
                mma_bf16(sa[2 * g + 1], aq[1], &bk[0][2]);
            }
        }

        // ---- online softmax (exp2 domain, MUFU ex2) ----
        float mt0 = -3.0e38f, mt1 = -3.0e38f;
        #pragma unroll
        for (int b = 0; b < 8; b++) {
            mt0 = fmaxf(mt0, fmaxf(sa[b][0], sa[b][1]));
            mt1 = fmaxf(mt1, fmaxf(sa[b][2], sa[b][3]));
        }
        mt0 = fmaxf(mt0, __shfl_xor_sync(0xffffffffu, mt0, 1));
        mt0 = fmaxf(mt0, __shfl_xor_sync(0xffffffffu, mt0, 2));
        mt1 = fmaxf(mt1, __shfl_xor_sync(0xffffffffu, mt1, 1));
        mt1 = fmaxf(mt1, __shfl_xor_sync(0xffffffffu, mt1, 2));
        const float mn0 = fmaxf(m0r, mt0), mn1 = fmaxf(m1r, mt1);
        const float al0 = ex2f(m0r - mn0), al1 = ex2f(m1r - mn1);
        m0r = mn0; m1r = mn1;
        float rs0 = 0.f, rs1 = 0.f;
        #pragma unroll
        for (int b = 0; b < 8; b++) {
            sa[b][0] = ex2f(sa[b][0] - mn0);
            sa[b][1] = ex2f(sa[b][1] - mn0);
            sa[b][2] = ex2f(sa[b][2] - mn1);
            sa[b][3] = ex2f(sa[b][3] - mn1);
            rs0 += sa[b][0] + sa[b][1];
            rs1 += sa[b][2] + sa[b][3];
        }
        rs0 += __shfl_xor_sync(0xffffffffu, rs0, 1);
        rs0 += __shfl_xor_sync(0xffffffffu, rs0, 2);
        rs1 += __shfl_xor_sync(0xffffffffu, rs1, 1);
        rs1 += __shfl_xor_sync(0xffffffffu, rs1, 2);
        l0r = l0r * al0 + rs0;
        l1r = l1r * al1 + rs1;
        #pragma unroll
        for (int b = 0; b < 8; b++) {
            oa[b][0] *= al0; oa[b][1] *= al0;
            oa[b][2] *= al1; oa[b][3] *= al1;
        }

        // ---- GEMM2: O += P V (fp16 P, single fp16 V) ----
        #pragma unroll
        for (int kb = 0; kb < 4; kb++) {
            uint32_t pp[4];
            pp[0] = packh2(sa[2 * kb][0],     sa[2 * kb][1]);
            pp[1] = packh2(sa[2 * kb][2],     sa[2 * kb][3]);
            pp[2] = packh2(sa[2 * kb + 1][0], sa[2 * kb + 1][1]);
            pp[3] = packh2(sa[2 * kb + 1][2], sa[2 * kb + 1][3]);
            #pragma unroll
            for (int g = 0; g < 4; g++) {
                uint32_t bv[4];
                const int trow = kb * 16 + (lane & 7) + ((lane >> 3) & 1) * 8;
                const int rbyte = g * 32 + ((lane >> 4) & 1) * 16;
                ldm_x4_t(bv, VOFF(buf) + swz(trow * 128 + rbyte));
                mma_f16(oa[2 * g],     pp, &bv[0]);
                mma_f16(oa[2 * g + 1], pp, &bv[2]);
            }
        }
    }

    // ---- epilogue: O/l -> g_oh single fp16 plane ----
    const float i0 = rcpf(l0r), i1 = rcpf(l1r);
    #pragma unroll
    for (int b = 0; b < 8; b++) {
        const int r   = b * 8 + (lane & 3) * 2;
        const int r0w = s0 + wid * 16 + (lane >> 2);
        size_t idx = zoff + (size_t)r0w * RR + r;
        *reinterpret_cast<uint32_t*>(&g_oh[idx]) =
            packh2(oa[b][0] * i0, oa[b][1] * i0);
        idx = zoff + (size_t)(r0w + 8) * RR + r;
        *reinterpret_cast<uint32_t*>(&g_oh[idx]) =
            packh2(oa[b][2] * i1, oa[b][3] * i1);
    }
    #undef QOFF
    #undef KOFF
    #undef VOFF
}

// ---------------------------------------------------------------------------
// Launch
// ---------------------------------------------------------------------------
extern "C" void kernel_launch(void* const* d_in, const int* in_sizes, int n_in,
                              void* d_out, int out_size)
{
    const float* q  = (const float*)d_in[0];
    const float* k  = (const float*)d_in[1];
    const float* v  = (const float*)d_in[2];
    const float* wq = (const float*)d_in[3];
    const float* wk = (const float*)d_in[4];
    const float* wv = (const float*)d_in[5];
    const float* wo = (const float*)d_in[6];
    float* out = (float*)d_out;

    (void)in_sizes; (void)n_in; (void)out_size;

    cudaFuncSetAttribute(gemm_kernel,
                         cudaFuncAttributeMaxDynamicSharedMemorySize, GEMM_SMEM);
    cudaFuncSetAttribute(f16gemm_kernel,
                         cudaFuncAttributeMaxDynamicSharedMemorySize, F16_SMEM);
    cudaFuncSetAttribute(attn_kernel,
                         cudaFuncAttributeMaxDynamicSharedMemorySize, ATT_SMEM);

    // 1) split inputs + weights
    conv_rows_kernel<<<dim3(1024, 3), 256>>>(q, k, v);
    conv_w_kernel<<<dim3(32, 32, 4), 256>>>(wq, wk, wv, wo);

    // 2) Q/K projections (bf16 3-term); V projection (fp16 2-term)
    gemm_kernel<<<dim3(8, 32, 2), 256, GEMM_SMEM>>>();
    f16gemm_kernel<<<dim3(8, 32), 256, F16_SMEM>>>(nullptr, 0);

    // 3) tensor-core flash attention -> g_oh
    attn_kernel<<<dim3(16, 32), 256, ATT_SMEM>>>();

    // 4) output projection (fp16 2-term) -> fp32 out
    f16gemm_kernel<<<dim3(8, 32), 256, F16_SMEM>>>(out, 1);
}

// round 17
// speedup vs baseline: 1.0437x; 1.0172x over previous
#include <cuda_runtime.h>
#include <cuda_bf16.h>
#include <cuda_fp16.h>
#include <cstdint>

// ---------------------------------------------------------------------------
// Problem constants
// ---------------------------------------------------------------------------
#define BB 2
#define SS 2048
#define DD 1024
#define HH 16
#define RR 64
#define BH (BB * HH)   // 32
#define NEL (BB * SS * DD)

// ---------------------------------------------------------------------------
// mma.sync helpers (baseline PTX, plain sm_100 target)
// ---------------------------------------------------------------------------
__device__ __forceinline__ uint32_t smem_u32(const void* p) {
    uint32_t a;
    asm("{ .reg .u64 t; cvta.to.shared.u64 t, %1; cvt.u32.u64 %0, t; }"
        : "=r"(a) : "l"(p));
    return a;
}
__device__ __forceinline__ void ldm_x4(uint32_t* r, uint32_t addr) {
    asm volatile("ldmatrix.sync.aligned.m8n8.x4.shared.b16 {%0,%1,%2,%3}, [%4];"
                 : "=r"(r[0]), "=r"(r[1]), "=r"(r[2]), "=r"(r[3]) : "r"(addr));
}
__device__ __forceinline__ void ldm_x4_t(uint32_t* r, uint32_t addr) {
    asm volatile("ldmatrix.sync.aligned.m8n8.x4.trans.shared.b16 {%0,%1,%2,%3}, [%4];"
                 : "=r"(r[0]), "=r"(r[1]), "=r"(r[2]), "=r"(r[3]) : "r"(addr));
}
__device__ __forceinline__ void mma_bf16(float* c, const uint32_t* a,
                                         const uint32_t* b) {
    asm volatile(
        "mma.sync.aligned.m16n8k16.row.col.f32.bf16.bf16.f32 "
        "{%0,%1,%2,%3}, {%4,%5,%6,%7}, {%8,%9}, {%0,%1,%2,%3};"
        : "+f"(c[0]), "+f"(c[1]), "+f"(c[2]), "+f"(c[3])
        : "r"(a[0]), "r"(a[1]), "r"(a[2]), "r"(a[3]), "r"(b[0]), "r"(b[1]));
}
__device__ __forceinline__ void mma_f16(float* c, const uint32_t* a,
                                        const uint32_t* b) {
    asm volatile(
        "mma.sync.aligned.m16n8k16.row.col.f32.f16.f16.f32 "
        "{%0,%1,%2,%3}, {%4,%5,%6,%7}, {%8,%9}, {%0,%1,%2,%3};"
        : "+f"(c[0]), "+f"(c[1]), "+f"(c[2]), "+f"(c[3])
        : "r"(a[0]), "r"(a[1]), "r"(a[2]), "r"(a[3]), "r"(b[0]), "r"(b[1]));
}
__device__ __forceinline__ void cp16(uint32_t dst, const void* src) {
    asm volatile("cp.async.cg.shared.global [%0], [%1], 16;"
                 :: "r"(dst), "l"(__cvta_generic_to_global(src)));
}
#define CP_COMMIT() asm volatile("cp.async.commit_group;" ::: "memory")
#define CP_WAIT0()  asm volatile("cp.async.wait_group 0;" ::: "memory")

__device__ __forceinline__ uint32_t swz(uint32_t o) { return o ^ ((o >> 3) & 0x70); }

__device__ __forceinline__ float ex2f(float x) {
    float y;
    asm("ex2.approx.ftz.f32 %0, %1;" : "=f"(y) : "f"(x));
    return y;
}
__device__ __forceinline__ float rcpf(float x) {
    float y;
    asm("rcp.approx.ftz.f32 %0, %1;" : "=f"(y) : "f"(x));
    return y;
}

// Split a float pair into bf16 hi/lo packed u32s (rn rounding).
__device__ __forceinline__ void splitpair(float x, float y,
                                          uint32_t& h, uint32_t& l) {
    asm("cvt.rn.bf16x2.f32 %0, %1, %2;" : "=r"(h) : "f"(y), "f"(x));
    float hx = __uint_as_float(h << 16);
    float hy = __uint_as_float(h & 0xFFFF0000u);
    asm("cvt.rn.bf16x2.f32 %0, %1, %2;" : "=r"(l) : "f"(y - hy), "f"(x - hx));
}
__device__ __forceinline__ uint32_t packh2(float x, float y) {
    __half2 H = __floats2half2_rn(x, y);
    return *reinterpret_cast<uint32_t*>(&H);
}

// ---------------------------------------------------------------------------
// Scratch
// ---------------------------------------------------------------------------
__device__ __nv_bfloat16 g_qs[2][NEL];
__device__ __nv_bfloat16 g_ks[2][NEL];
__device__ __half        g_vh16[NEL];           // v input, single fp16 plane
__device__ __nv_bfloat16 g_wqT[2][DD * DD];
__device__ __nv_bfloat16 g_wkT[2][DD * DD];
__device__ __half        g_wvH[2][DD * DD];     // wv fp16 hi/lo, transposed
__device__ __half        g_woH[2][DD * DD];     // wo fp16 hi/lo, transposed
// projection outputs, [b,h,s,r] layout:
//   Q/K bf16 hi/lo planes (Q pre-scaled by 0.125*log2e, exp2 domain)
//   V  single fp16 plane
__device__ __nv_bfloat16 g_Qb[2][BH * SS * RR];
__device__ __nv_bfloat16 g_Kb[2][BH * SS * RR];
__device__ __half        g_Vh[BH * SS * RR];
// attention output, single fp16 plane, [z][s][r] == flat [4096][1024]
__device__ __half        g_oh[NEL];

// ---------------------------------------------------------------------------
// fp32 -> split converters. sel 0/1 (q,k): bf16 hi/lo. sel 2 (v): fp16 single.
// ---------------------------------------------------------------------------
__global__ void __launch_bounds__(256) conv_rows_kernel(
    const float* __restrict__ q, const float* __restrict__ k,
    const float* __restrict__ v)
{
    const int sel = blockIdx.y;
    const float* src = (sel == 0) ? q : (sel == 1) ? k : v;

    if (sel < 2) {
        __nv_bfloat16* d0 = (sel == 0) ? g_qs[0] : g_ks[0];
        __nv_bfloat16* d1 = (sel == 0) ? g_qs[1] : g_ks[1];
        for (int i = (blockIdx.x * blockDim.x + threadIdx.x) * 4; i < NEL;
             i += gridDim.x * blockDim.x * 4) {
            float4 x = *reinterpret_cast<const float4*>(src + i);
            uint32_t h0, l0, h1, l1;
            splitpair(x.x, x.y, h0, l0);
            splitpair(x.z, x.w, h1, l1);
            *reinterpret_cast<uint2*>(d0 + i) = make_uint2(h0, h1);
            *reinterpret_cast<uint2*>(d1 + i) = make_uint2(l0, l1);
        }
    } else {
        for (int i = (blockIdx.x * blockDim.x + threadIdx.x) * 4; i < NEL;
             i += gridDim.x * blockDim.x * 4) {
            float4 x = *reinterpret_cast<const float4*>(src + i);
            *reinterpret_cast<uint2*>(g_vh16 + i) =
                make_uint2(packh2(x.x, x.y), packh2(x.z, x.w));
        }
    }
}

// Weight transpose + split. sel 0/1: bf16 planes; sel 2 (wv) / 3 (wo): fp16.
__global__ void __launch_bounds__(256) conv_w_kernel(
    const float* __restrict__ wq, const float* __restrict__ wk,
    const float* __restrict__ wv, const float* __restrict__ wo)
{
    const int sel = blockIdx.z;
    const float* W = (sel == 0) ? wq : (sel == 1) ? wk : (sel == 2) ? wv : wo;

    __shared__ float tile[32][33];
    const int tx = threadIdx.x & 31;
    const int ty = threadIdx.x >> 5;
    const int ct = blockIdx.x;
    const int rt = blockIdx.y;

    #pragma unroll
    for (int i = 0; i < 4; i++) {
        const int d = rt * 32 + ty + i * 8;
        const int n = ct * 32 + tx;
        size_t idx;
        if (sel < 3) idx = ((size_t)(n >> 6) * DD + d) * RR + (n & 63);
        else         idx = (size_t)d * DD + n;
        tile[ty + i * 8][tx] = W[idx];
    }
    __syncthreads();
    #pragma unroll
    for (int i = 0; i < 4; i++) {
        const int nl = ty + i * 8;
        const int n  = ct * 32 + nl;
        const int d  = rt * 32 + tx;
        float x = tile[tx][nl];
        size_t o = (size_t)n * DD + d;
        if (sel < 2) {
            __nv_bfloat16* d0 = (sel == 0) ? g_wqT[0] : g_wkT[0];
            __nv_bfloat16* d1 = (sel == 0) ? g_wqT[1] : g_wkT[1];
            __nv_bfloat16 b0 = __float2bfloat16(x);
            d0[o] = b0;
            d1[o] = __float2bfloat16(x - __bfloat162float(b0));
        } else {
            __half* d0 = (sel == 2) ? g_wvH[0] : g_woH[0];
            __half* d1 = (sel == 2) ? g_wvH[1] : g_woH[1];
            __half h0 = __float2half_rn(x);
            d0[o] = h0;
            d1[o] = __float2half_rn(x - __half2float(h0));
        }
    }
}

// ---------------------------------------------------------------------------
// fp16 2-term GEMM body (R14 config: 128x128 tile, 2-stage, 64KB smem).
//   kind 0: -> g_Vh packed [b,h,s,r];  kind 1: -> fp32 outC.
// ---------------------------------------------------------------------------
#define GEMM_SMEM 65536

__device__ __forceinline__ void f16_body(
    const __half* __restrict__ Ag,
    const __half* __restrict__ B0, const __half* __restrict__ B1,
    float* __restrict__ outC, int kind, char* smem,
    int bx, int by)
{
    const __half* Bp[2] = {B0, B1};
    const int NST = 32;
    const uint32_t sb = smem_u32(smem);
    const int t      = threadIdx.x;
    const int lane   = t & 31;
    const int wid    = t >> 5;
    const int warp_m = wid >> 2;
    const int warp_n = wid & 3;
    const int m0 = by * 128;
    const int n0 = bx * 128;

    float acc[4][4][4];
    #pragma unroll
    for (int a = 0; a < 4; a++)
        #pragma unroll
        for (int b = 0; b < 4; b++)
            #pragma unroll
            for (int c = 0; c < 4; c++) acc[a][b][c] = 0.f;

    const int a_row  = warp_m * 64 + (lane & 15);
    const int a_koff = (lane >> 4) * 16;
    const int b_row  = warp_n * 32 + (lane & 7) + ((lane >> 4) & 1) * 8;
    const int b_koff = ((lane >> 3) & 1) * 16;

    {
        const uint32_t abase = sb, bbase = sb + 16384;
        #pragma unroll
        for (int it = 0; it < 4; it++) {
            const int cid = it * 256 + t;
            const int row = cid >> 3, c16 = cid & 7;
            cp16(abase + swz(row * 128 + c16 * 16),
                 Ag + (size_t)(m0 + row) * DD + c16 * 8);
            cp16(bbase + swz(row * 128 + c16 * 16),
                 Bp[0] + (size_t)(n0 + row) * DD + c16 * 8);
        }
        CP_COMMIT();
    }

    for (int s = 0; s < NST; s++) {
        CP_WAIT0();
        __syncthreads();
        if (s + 1 < NST) {
            const int sn = s + 1;
            const int tt = sn >> 4;
            const int k0 = (sn & 15) * 64;
            const uint32_t abase = sb + (sn & 1) * 32768;
            const uint32_t bbase = abase + 16384;
            #pragma unroll
            for (int it = 0; it < 4; it++) {
                const int cid = it * 256 + t;
                const int row = cid >> 3, c16 = cid & 7;
                cp16(abase + swz(row * 128 + c16 * 16),
                     Ag + (size_t)(m0 + row) * DD + k0 + c16 * 8);
                cp16(bbase + swz(row * 128 + c16 * 16),
                     Bp[tt] + (size_t)(n0 + row) * DD + k0 + c16 * 8);
            }
            CP_COMMIT();
        }
        const uint32_t abase = sb + (s & 1) * 32768;
        const uint32_t bbase = abase + 16384;
        #pragma unroll
        for (int k16 = 0; k16 < 64; k16 += 16) {
            uint32_t ar[4][4], br[4][2];
            #pragma unroll
            for (int mi = 0; mi < 4; mi++) {
                const int row = a_row + mi * 16;
                ldm_x4(ar[mi], abase + swz(row * 128 + k16 * 2 + a_koff));
            }
            #pragma unroll
            for (int nb = 0; nb < 2; nb++) {
                const int n = b_row + nb * 16;
                uint32_t r[4];
                ldm_x4(r, bbase + swz(n * 128 + k16 * 2 + b_koff));
                br[nb * 2][0] = r[0]; br[nb * 2][1] = r[1];
                br[nb * 2 + 1][0] = r[2]; br[nb * 2 + 1][1] = r[3];
            }
            #pragma unroll
            for (int mi = 0; mi < 4; mi++)
                #pragma unroll
                for (int ni = 0; ni < 4; ni++)
                    mma_f16(acc[mi][ni], ar[mi], br[ni]);
        }
    }

    #pragma unroll
    for (int mi = 0; mi < 4; mi++) {
        #pragma unroll
        for (int ni = 0; ni < 4; ni++) {
            const int r0 = m0 + warp_m * 64 + mi * 16 + (lane >> 2);
            const int c  = n0 + warp_n * 32 + ni * 8 + (lane & 3) * 2;
            #pragma unroll
            for (int half = 0; half < 2; half++) {
                const int m = r0 + half * 8;
                float v0 = acc[mi][ni][half * 2];
                float v1 = acc[mi][ni][half * 2 + 1];
                if (kind == 0) {
                    const int h = c >> 6, r = c & 63;
                    const int b = m >> 11, sl = m & 2047;
                    size_t idx = (((size_t)b * HH + h) * SS + sl) * RR + r;
                    *reinterpret_cast<uint32_t*>(&g_Vh[idx]) = packh2(v0, v1);
                } else {
                    *reinterpret_cast<float2*>(&outC[(size_t)m * DD + c]) =
                        make_float2(v0, v1);
                }
            }
        }
    }
}

// ---------------------------------------------------------------------------
// Unified projection kernel. grid (8, 32, 3):
//   z 0/1: Q/K — split-bf16 3-term, 48 stages -> bf16 hi/lo planes
//   z 2  : V   — fp16 2-term (f16_body kind 0)
// One launch packs 768 CTAs (2.6 waves) instead of two partial-wave tails.
// ---------------------------------------------------------------------------
__global__ void __launch_bounds__(256) proj_kernel()
{
    extern __shared__ char smem[];
    const int kind = blockIdx.z;
    if (kind == 2) {
        f16_body(g_vh16, g_wvH[0], g_wvH[1], nullptr, 0, smem,
                 blockIdx.x, blockIdx.y);
        return;
    }

    const __nv_bfloat16 *Ax[2], *Bx[2];
    __nv_bfloat16 *P0, *P1;
    float scale = 1.0f;
    if (kind == 0) { Ax[0] = g_qs[0]; Ax[1] = g_qs[1];
                     Bx[0] = g_wqT[0]; Bx[1] = g_wqT[1];
                     P0 = g_Qb[0]; P1 = g_Qb[1];
                     scale = 0.125f * 1.4426950408889634f; }
    else           { Ax[0] = g_ks[0]; Ax[1] = g_ks[1];
                     Bx[0] = g_wkT[0]; Bx[1] = g_wkT[1];
                     P0 = g_Kb[0]; P1 = g_Kb[1]; }
    const int ti[3] = {0, 0, 1};
    const int tj[3] = {0, 1, 0};
    const int NST = 48;

    const uint32_t sb = smem_u32(smem);
    const int t      = threadIdx.x;
    const int lane   = t & 31;
    const int wid    = t >> 5;
    const int warp_m = wid >> 2;
    const int warp_n = wid & 3;
    const int m0 = blockIdx.y * 128;
    const int n0 = blockIdx.x * 128;

    float acc[4][4][4];
    #pragma unroll
    for (int a = 0; a < 4; a++)
        #pragma unroll
        for (int b = 0; b < 4; b++)
            #pragma unroll
            for (int c = 0; c < 4; c++) acc[a][b][c] = 0.f;

    const int a_row  = warp_m * 64 + (lane & 15);
    const int a_koff = (lane >> 4) * 16;
    const int b_row  = warp_n * 32 + (lane & 7) + ((lane >> 4) & 1) * 8;
    const int b_koff = ((lane >> 3) & 1) * 16;

    {
        const uint32_t abase = sb, bbase = sb + 16384;
        #pragma unroll
        for (int it = 0; it < 4; it++) {
            const int cid = it * 256 + t;
            const int row = cid >> 3, c16 = cid & 7;
            cp16(abase + swz(row * 128 + c16 * 16),
                 Ax[0] + (size_t)(m0 + row) * DD + c16 * 8);
            cp16(bbase + swz(row * 128 + c16 * 16),
                 Bx[0] + (size_t)(n0 + row) * DD + c16 * 8);
        }
        CP_COMMIT();
    }

    for (int s = 0; s < NST; s++) {
        CP_WAIT0();
        __syncthreads();
        if (s + 1 < NST) {
            const int sn = s + 1;
            const int tt = sn >> 4;
            const int k0 = (sn & 15) * 64;
            const __nv_bfloat16* Ag = Ax[ti[tt]];
            const __nv_bfloat16* Bg = Bx[tj[tt]];
            const uint32_t abase = sb + (sn & 1) * 32768;
            const uint32_t bbase = abase + 16384;
            #pragma unroll
            for (int it = 0; it < 4; it++) {
                const int cid = it * 256 + t;
                const int row = cid >> 3, c16 = cid & 7;
                cp16(abase + swz(row * 128 + c16 * 16),
                     Ag + (size_t)(m0 + row) * DD + k0 + c16 * 8);
                cp16(bbase + swz(row * 128 + c16 * 16),
                     Bg + (size_t)(n0 + row) * DD + k0 + c16 * 8);
            }
            CP_COMMIT();
        }
        const uint32_t abase = sb + (s & 1) * 32768;
        const uint32_t bbase = abase + 16384;
        #pragma unroll
        for (int k16 = 0; k16 < 64; k16 += 16) {
            uint32_t ar[4][4], br[4][2];
            #pragma unroll
            for (int mi = 0; mi < 4; mi++) {
                const int row = a_row + mi * 16;
                ldm_x4(ar[mi], abase + swz(row * 128 + k16 * 2 + a_koff));
            }
            #pragma unroll
            for (int nb = 0; nb < 2; nb++) {
                const int n = b_row + nb * 16;
                uint32_t r[4];
                ldm_x4(r, bbase + swz(n * 128 + k16 * 2 + b_koff));
                br[nb * 2][0] = r[0]; br[nb * 2][1] = r[1];
                br[nb * 2 + 1][0] = r[2]; br[nb * 2 + 1][1] = r[3];
            }
            #pragma unroll
            for (int mi = 0; mi < 4; mi++)
                #pragma unroll
                for (int ni = 0; ni < 4; ni++)
                    mma_bf16(acc[mi][ni], ar[mi], br[ni]);
        }
    }

    // epilogue -> bf16 hi/lo planes in [b,h,s,r]
    #pragma unroll
    for (int mi = 0; mi < 4; mi++) {
        #pragma unroll
        for (int ni = 0; ni < 4; ni++) {
            const int r0 = m0 + warp_m * 64 + mi * 16 + (lane >> 2);
            const int c  = n0 + warp_n * 32 + ni * 8 + (lane & 3) * 2;
            #pragma unroll
            for (int half = 0; half < 2; half++) {
                const int m = r0 + half * 8;
                float v0 = acc[mi][ni][half * 2] * scale;
                float v1 = acc[mi][ni][half * 2 + 1] * scale;
                const int h = c >> 6, r = c & 63;
                const int b = m >> 11, sl = m & 2047;
                size_t idx = (((size_t)b * HH + h) * SS + sl) * RR + r;
                uint32_t hh, ll;
                splitpair(v0, v1, hh, ll);
                *reinterpret_cast<uint32_t*>(&P0[idx]) = hh;
                *reinterpret_cast<uint32_t*>(&P1[idx]) = ll;
            }
        }
    }
}

// ---------------------------------------------------------------------------
// Output projection launch wrapper (f16_body kind 1).
// ---------------------------------------------------------------------------
__global__ void __launch_bounds__(256) out_kernel(float* __restrict__ outC)
{
    extern __shared__ char smem[];
    f16_body(g_oh, g_woH[0], g_woH[1], outC, 1, smem,
             blockIdx.x, blockIdx.y);
}

// ---------------------------------------------------------------------------
// Tensor-core flash attention (unchanged from the 483us version).
// ---------------------------------------------------------------------------
#define ATT_SMEM 81920

__global__ void __launch_bounds__(256, 2) attn_kernel()
{
    const int z  = blockIdx.y;
    const int s0 = blockIdx.x * 128;
    extern __shared__ char sm[];
    const uint32_t sb = smem_u32(sm);
    const int t = threadIdx.x, lane = t & 31, wid = t >> 5;
    const size_t zoff = (size_t)z * SS * RR;

    #define QOFF(p)      (sb + (p) * 16384u)
    #define KOFF(bf, p)  (sb + 32768u + (bf) * 24576u + (p) * 8192u)
    #define VOFF(bf)     (sb + 32768u + (bf) * 24576u + 16384u)

    #pragma unroll
    for (int p = 0; p < 2; p++) {
        const __nv_bfloat16* src = g_Qb[p] + zoff + (size_t)s0 * RR;
        #pragma unroll
        for (int it = 0; it < 4; it++) {
            const int cid = it * 256 + t;
            const int row = cid >> 3, c16 = cid & 7;
            cp16(QOFF(p) + swz(row * 128 + c16 * 16), src + row * 64 + c16 * 8);
        }
    }
    #pragma unroll
    for (int it = 0; it < 2; it++) {
        const int cid = it * 256 + t;
        const int row = cid >> 3, c16 = cid & 7;
        cp16(KOFF(0, 0) + swz(row * 128 + c16 * 16),
             g_Kb[0] + zoff + (size_t)row * RR + c16 * 8);
        cp16(KOFF(0, 1) + swz(row * 128 + c16 * 16),
             g_Kb[1] + zoff + (size_t)row * RR + c16 * 8);
        cp16(VOFF(0) + swz(row * 128 + c16 * 16),
             g_Vh + zoff + (size_t)row * RR + c16 * 8);
    }
    CP_COMMIT();

    float m0r = -3.0e38f, m1r = -3.0e38f, l0r = 0.f, l1r = 0.f;
    float oa[8][4];
    #pragma unroll
    for (int b = 0; b < 8; b++)
        #pragma unroll
        for (int c = 0; c < 4; c++) oa[b][c] = 0.f;

    for (int s = 0; s < 32; s++) {
        const int buf = s & 1;
        CP_WAIT0();
        __syncthreads();
        if (s + 1 < 32) {
            const int nb = (s + 1) & 1;
            const int kv = (s + 1) * 64;
            #pragma unroll
            for (int it = 0; it < 2; it++) {
                const int cid = it * 256 + t;
                const int row = cid >> 3, c16 = cid & 7;
                cp16(KOFF(nb, 0) + swz(row * 128 + c16 * 16),
                     g_Kb[0] + zoff + (size_t)(kv + row) * RR + c16 * 8);
                cp16(KOFF(nb, 1) + swz(row * 128 + c16 * 16),
                     g_Kb[1] + zoff + (size_t)(kv + row) * RR + c16 * 8);
                cp16(VOFF(nb) + swz(row * 128 + c16 * 16),
                     g_Vh + zoff + (size_t)(kv + row) * RR + c16 * 8);
            }
            CP_COMMIT();
        }

        // ---- GEMM1: S = Q K^T (bf16, 3 split terms) ----
        float sa[8][4];
        #pragma unroll
        for (int b = 0; b < 8; b++)
            #pragma unroll
            for (int c = 0; c < 4; c++) sa[b][c] = 0.f;

        #pragma unroll
        for (int kb = 0; kb < 4; kb++) {
            uint32_t aq[2][4];
            const int arow = wid * 16 + (lane & 15);
            const int akoff = kb * 32 + (lane >> 4) * 16;
            #pragma unroll
            for (int p = 0; p < 2; p++)
                ldm_x4(aq[p], QOFF(p) + swz(arow * 128 + akoff));
            #pragma unroll
            for (int g = 0; g < 4; g++) {
                uint32_t bk[2][4];
                const int brow = g * 16 + (lane & 7) + ((lane >> 4) & 1) * 8;
                const int bkoff = kb * 32 + ((lane >> 3) & 1) * 16;
                #pragma unroll
                for (int p = 0; p < 2; p++)
                    ldm_x4(bk[p], KOFF(buf, p) + swz(brow * 128 + bkoff));
                mma_bf16(sa[2 * g],     aq[0], &bk[0][0]);   // hi*hi
                mma_bf16(sa[2 * g + 1], aq[0], &bk[0][2]);
                mma_bf16(sa[2 * g],     aq[0], &bk[1][0]);   // hi*lo
                mma_bf16(sa[2 * g + 1], aq[0], &bk[1][2]);
                mma_bf16(sa[2 * g],     aq[1], &bk[0][0]);   // lo*hi
                mma_bf16(sa[2 * g + 1], aq[1], &bk[0][2]);
            }
        }

        // ---- online softmax (exp2 domain, MUFU ex2) ----
        float mt0 = -3.0e38f, mt1 = -3.0e38f;
        #pragma unroll
        for (int b = 0; b < 8; b++) {
            mt0 = fmaxf(mt0, fmaxf(sa[b][0], sa[b][1]));
            mt1 = fmaxf(mt1, fmaxf(sa[b][2], sa[b][3]));
        }
        mt0 = fmaxf(mt0, __shfl_xor_sync(0xffffffffu, mt0, 1));
        mt0 = fmaxf(mt0, __shfl_xor_sync(0xffffffffu, mt0, 2));
        mt1 = fmaxf(mt1, __shfl_xor_sync(0xffffffffu, mt1, 1));
        mt1 = fmaxf(mt1, __shfl_xor_sync(0xffffffffu, mt1, 2));
        const float mn0 = fmaxf(m0r, mt0), mn1 = fmaxf(m1r, mt1);
        const float al0 = ex2f(m0r - mn0), al1 = ex2f(m1r - mn1);
        m0r = mn0; m1r = mn1;
        float rs0 = 0.f, rs1 = 0.f;
        #pragma unroll
        for (int b = 0; b < 8; b++) {
            sa[b][0] = ex2f(sa[b][0] - mn0);
            sa[b][1] = ex2f(sa[b][1] - mn0);
            sa[b][2] = ex2f(sa[b][2] - mn1);
            sa[b][3] = ex2f(sa[b][3] - mn1);
            rs0 += sa[b][0] + sa[b][1];
            rs1 += sa[b][2] + sa[b][3];
        }
        rs0 += __shfl_xor_sync(0xffffffffu, rs0, 1);
        rs0 += __shfl_xor_sync(0xffffffffu, rs0, 2);
        rs1 += __shfl_xor_sync(0xffffffffu, rs1, 1);
        rs1 += __shfl_xor_sync(0xffffffffu, rs1, 2);
        l0r = l0r * al0 + rs0;
        l1r = l1r * al1 + rs1;
        #pragma unroll
        for (int b = 0; b < 8; b++) {
            oa[b][0] *= al0; oa[b][1] *= al0;
            oa[b][2] *= al1; oa[b][3] *= al1;
        }

        // ---- GEMM2: O += P V (fp16 P, single fp16 V) ----
        #pragma unroll
        for (int kb = 0; kb < 4; kb++) {
            uint32_t pp[4];
            pp[0] = packh2(sa[2 * kb][0],     sa[2 * kb][1]);
            pp[1] = packh2(sa[2 * kb][2],     sa[2 * kb][3]);
            pp[2] = packh2(sa[2 * kb + 1][0], sa[2 * kb + 1][1]);
            pp[3] = packh2(sa[2 * kb + 1][2], sa[2 * kb + 1][3]);
            #pragma unroll
            for (int g = 0; g < 4; g++) {
                uint32_t bv[4];
                const int trow = kb * 16 + (lane & 7) + ((lane >> 3) & 1) * 8;
                const int rbyte = g * 32 + ((lane >> 4) & 1) * 16;
                ldm_x4_t(bv, VOFF(buf) + swz(trow * 128 + rbyte));
                mma_f16(oa[2 * g],     pp, &bv[0]);
                mma_f16(oa[2 * g + 1], pp, &bv[2]);
            }
        }
    }

    // ---- epilogue: O/l -> g_oh single fp16 plane ----
    const float i0 = rcpf(l0r), i1 = rcpf(l1r);
    #pragma unroll
    for (int b = 0; b < 8; b++) {
        const int r   = b * 8 + (lane & 3) * 2;
        const int r0w = s0 + wid * 16 + (lane >> 2);
        size_t idx = zoff + (size_t)r0w * RR + r;
        *reinterpret_cast<uint32_t*>(&g_oh[idx]) =
            packh2(oa[b][0] * i0, oa[b][1] * i0);
        idx = zoff + (size_t)(r0w + 8) * RR + r;
        *reinterpret_cast<uint32_t*>(&g_oh[idx]) =
            packh2(oa[b][2] * i1, oa[b][3] * i1);
    }
    #undef QOFF
    #undef KOFF
    #undef VOFF
}

// ---------------------------------------------------------------------------
// Launch
// ---------------------------------------------------------------------------
extern "C" void kernel_launch(void* const* d_in, const int* in_sizes, int n_in,
                              void* d_out, int out_size)
{
    const float* q  = (const float*)d_in[0];
    const float* k  = (const float*)d_in[1];
    const float* v  = (const float*)d_in[2];
    const float* wq = (const float*)d_in[3];
    const float* wk = (const float*)d_in[4];
    const float* wv = (const float*)d_in[5];
    const float* wo = (const float*)d_in[6];
    float* out = (float*)d_out;

    (void)in_sizes; (void)n_in; (void)out_size;

    cudaFuncSetAttribute(proj_kernel,
                         cudaFuncAttributeMaxDynamicSharedMemorySize, GEMM_SMEM);
    cudaFuncSetAttribute(out_kernel,
                         cudaFuncAttributeMaxDynamicSharedMemorySize, GEMM_SMEM);
    cudaFuncSetAttribute(attn_kernel,
                         cudaFuncAttributeMaxDynamicSharedMemorySize, ATT_SMEM);

    // 1) split inputs + weights
    conv_rows_kernel<<<dim3(1024, 3), 256>>>(q, k, v);
    conv_w_kernel<<<dim3(32, 32, 4), 256>>>(wq, wk, wv, wo);

    // 2) unified Q/K/V projections (one launch, 768 CTAs)
    proj_kernel<<<dim3(8, 32, 3), 256, GEMM_SMEM>>>();

    // 3) tensor-core flash attention -> g_oh
    attn_kernel<<<dim3(16, 32), 256, ATT_SMEM>>>();

    // 4) output projection (fp16 2-term) -> fp32 out
    out_kernel<<<dim3(8, 32), 256, GEMM_SMEM>>>(out);
}